// round 12
// baseline (speedup 1.0000x reference)
#include <cuda_runtime.h>
#include <cuda_fp16.h>
#include <mma.h>
#include <cstdint>
#include <cstddef>
using namespace nvcuda;

#define NNODES 55296
#define NEDGES 221184
#define N32 (NNODES * 32)
#define NW 13824  // warps in pre/h0 node pass (1728 blocks x 8)

// ------------------------- device scratch -----------------------------------
__device__ __align__(256) float g_h[2 * N32];
__device__ __align__(256) float g_agg[2 * N32];
__device__ __align__(256) __half g_tA[(size_t)NEDGES * 32];   // t hi fp16
__device__ __align__(256) __half g_Bt[32 * 1024];             // B' permuted
__device__ __align__(256) float g_biasp[1024];                // eb2 permuted
__device__ __align__(256) __half g_We[(size_t)NEDGES * 1024]; // [e][j] j=(q,o,hl)

__device__ __forceinline__ float frcp(float x) {
    float r;
    asm("rcp.approx.f32 %0, %1;" : "=f"(r) : "f"(x));
    return r;
}
__device__ __forceinline__ float fsig(float x) { return frcp(1.f + __expf(-x)); }
__device__ __forceinline__ float ftanh(float x) {
    return 1.f - 2.f * frcp(1.f + __expf(2.f * x));
}
__device__ __forceinline__ uint64_t mkpol_ef() {
    uint64_t p;
    asm("createpolicy.fractional.L2::evict_first.b64 %0;" : "=l"(p));
    return p;
}
__device__ __forceinline__ uint4 ld_ef(const void* gp, uint64_t pol) {
    uint4 v;
    asm volatile("ld.global.nc.L2::cache_hint.v4.u32 {%0,%1,%2,%3}, [%4], %5;"
                 : "=r"(v.x), "=r"(v.y), "=r"(v.z), "=r"(v.w)
                 : "l"(gp), "l"(pol));
    return v;
}
__device__ __forceinline__ void st_ef(void* gp, uint4 v, uint64_t pol) {
    asm volatile("st.global.L2::cache_hint.v4.b32 [%0], {%1,%2,%3,%4}, %5;"
                 :: "l"(gp), "r"(v.x), "r"(v.y), "r"(v.z), "r"(v.w), "l"(pol)
                 : "memory");
}

// ---- launch 0: fused pre: B' build + bias permute + t build + h0 + zero ----
__global__ __launch_bounds__(256) void pre_kernel(
    const float* __restrict__ ew2, const float* __restrict__ eb2,
    const float4* __restrict__ rel4, const float* __restrict__ ew1,
    const float* __restrict__ eb1, const float* __restrict__ x,
    const float* __restrict__ pw1, const float* __restrict__ pb1,
    const float* __restrict__ pw2, const float* __restrict__ pb2) {
    int b = blockIdx.x, tid = threadIdx.x;
    if (b < 128) {               // B' [32][1024]: col j = q*256+o*8+hl
        int i = b * 256 + tid;
        int k = i >> 10, j = i & 1023;
        int h = ((j >> 8) << 3) + (j & 7), o = (j >> 3) & 31;
        g_Bt[i] = __float2half(ew2[k * 1024 + h * 32 + o]);
    } else if (b == 128) {       // permuted bias
#pragma unroll
        for (int u = 0; u < 4; u++) {
            int j = tid * 4 + u;
            int h = ((j >> 8) << 3) + (j & 7), o = (j >> 3) & 31;
            g_biasp[j] = eb2[h * 32 + o];
        }
    } else if (b < 129 + 27648) {  // t = relu(rel@ew1+eb1) -> fp16
        int g = (b - 129) * 256 + tid;
        int e = g >> 5, k = g & 31;
        float4 r = rel4[e];
        float v = eb1[k] + r.x * ew1[k] + r.y * ew1[32 + k] +
                  r.z * ew1[64 + k] + r.w * ew1[96 + k];
        g_tA[(size_t)e * 32 + k] = __float2half(fmaxf(v, 0.f));
    } else {                     // h0 projection + zero g_agg (8 nodes/warp)
        int hb = b - 129 - 27648;  // 0..1727
        __shared__ float sW1[1024], sW2[1024];
        int lane = tid & 31;
#pragma unroll
        for (int i = 0; i < 8; i++)
            g_agg[hb * 256 + tid + i * 442368] = 0.f;
        for (int i = tid; i < 1024; i += 256) { sW1[i] = pw1[i]; sW2[i] = pw2[i]; }
        __syncthreads();
        int wbase = hb * 8 + (tid >> 5);
#pragma unroll 1
        for (int it = 0; it < 8; it++) {
            int gw = wbase + it * NW;
            float xr = x[(size_t)gw * 32 + lane];
            float t1 = pb1[lane];
#pragma unroll
            for (int h = 0; h < 32; h++)
                t1 = fmaf(__shfl_sync(0xffffffffu, xr, h), sW1[h * 32 + lane], t1);
            t1 = fmaxf(t1, 0.f);
            float o = pb2[lane];
#pragma unroll
            for (int h = 0; h < 32; h++)
                o = fmaf(__shfl_sync(0xffffffffu, t1, h), sW2[h * 32 + lane], o);
            g_h[(size_t)gw * 32 + lane] = o;
        }
    }
}

// ---- launch 1: We GEMM [128x32]@[32x1024] wmma (measured 187us, unchanged) --
#define SA 0                 // 128*40*2  = 10240
#define SB 10240             // 32*1032*2 = 66048
#define SC 76288             // 8*16*68*4 = 34816
#define SBIAS 111104         // 4096
#define STOT 115200

__global__ __launch_bounds__(256, 2) void we_wmma_kernel() {
    extern __shared__ char sm[];
    __half* sA = (__half*)(sm + SA);
    __half* sB = (__half*)(sm + SB);
    float* sC = (float*)(sm + SC);
    float* sBias = (float*)(sm + SBIAS);
    int tid = threadIdx.x, wid = tid >> 5, lane = tid & 31;
    uint64_t pol = mkpol_ef();

    const uint4* ga = (const uint4*)(g_tA + (size_t)blockIdx.x * 128 * 32);
#pragma unroll
    for (int r = 0; r < 2; r++) {
        int i = tid + r * 256, row = i >> 2, c = i & 3;
        *(uint4*)(sA + row * 40 + c * 8) = ga[i];
    }
    const uint4* gb = (const uint4*)(const void*)g_Bt;
#pragma unroll
    for (int r = 0; r < 16; r++) {
        int i = tid + r * 256, row = i >> 7, c = i & 127;
        *(uint4*)(sB + row * 1032 + c * 8) = gb[i];
    }
#pragma unroll
    for (int r = 0; r < 4; r++) sBias[tid + r * 256] = g_biasp[tid + r * 256];
    __syncthreads();

    float* sCw = sC + wid * 16 * 68;
    const int rsub = lane >> 3, ch = lane & 7;
    for (int nt = 0; nt < 16; nt++) {
        wmma::fragment<wmma::accumulator, 16, 16, 16, float> acc[4];
#pragma unroll
        for (int f = 0; f < 4; f++) wmma::fill_fragment(acc[f], 0.f);
#pragma unroll
        for (int k = 0; k < 2; k++) {
            wmma::fragment<wmma::matrix_a, 16, 16, 16, __half, wmma::row_major> af;
            wmma::load_matrix_sync(af, sA + (wid * 16) * 40 + k * 16, 40);
#pragma unroll
            for (int f = 0; f < 4; f++) {
                wmma::fragment<wmma::matrix_b, 16, 16, 16, __half, wmma::row_major> bf;
                wmma::load_matrix_sync(bf, sB + (k * 16) * 1032 + nt * 64 + f * 16,
                                       1032);
                wmma::mma_sync(acc[f], af, bf, acc[f]);
            }
        }
        __syncwarp();
#pragma unroll
        for (int f = 0; f < 4; f++)
            wmma::store_matrix_sync(sCw + f * 16, acc[f], 68, wmma::mem_row_major);
        __syncwarp();
        const float* bp = sBias + nt * 64 + ch * 8;
#pragma unroll
        for (int p = 0; p < 4; p++) {
            int row = p * 4 + rsub;
            const float* rp = sCw + row * 68 + ch * 8;
            float4 v0 = *(const float4*)rp;
            float4 v1 = *(const float4*)(rp + 4);
            __half2 a = __floats2half2_rn(v0.x + bp[0], v0.y + bp[1]);
            __half2 b2 = __floats2half2_rn(v0.z + bp[2], v0.w + bp[3]);
            __half2 c2 = __floats2half2_rn(v1.x + bp[4], v1.y + bp[5]);
            __half2 d2 = __floats2half2_rn(v1.z + bp[6], v1.w + bp[7]);
            int e = blockIdx.x * 128 + wid * 16 + row;
            uint4 pk = make_uint4(*(uint32_t*)&a, *(uint32_t*)&b2,
                                  *(uint32_t*)&c2, *(uint32_t*)&d2);
            st_ef((char*)(void*)g_We + (size_t)e * 2048 + nt * 128 + ch * 16, pk,
                  pol);
        }
        __syncwarp();
    }
}

// ---- msg + scatter, 2 edges per warp (DRAM-bound, ~roofline, unchanged) -----
__global__ __launch_bounds__(256) void msg_kernel(const int* __restrict__ src,
                                                  const int* __restrict__ dst) {
    __shared__ __align__(16) float ns[8][4][32];
    const int w = threadIdx.x >> 5, lane = threadIdx.x & 31;
    const int e0 = blockIdx.x * 16 + w * 2;
    uint64_t pol = mkpol_ef();
    int s0 = __ldg(&src[e0]), s1 = __ldg(&src[e0 + 1]);
    int d0 = __ldg(&dst[e0]), d1 = __ldg(&dst[e0 + 1]);
    ns[w][0][lane] = g_h[(size_t)s0 * 32 + lane];
    ns[w][1][lane] = g_h[N32 + (size_t)s0 * 32 + lane];
    ns[w][2][lane] = g_h[(size_t)s1 * 32 + lane];
    ns[w][3][lane] = g_h[N32 + (size_t)s1 * 32 + lane];
    uint4 q[8];
#pragma unroll
    for (int ee = 0; ee < 2; ee++)
#pragma unroll
        for (int qi = 0; qi < 4; qi++)
            q[ee * 4 + qi] = ld_ef((const char*)(const void*)g_We +
                                       (size_t)(e0 + ee) * 2048 + qi * 512 +
                                       lane * 16,
                                   pol);
    __syncwarp();
    float acc[4] = {0.f, 0.f, 0.f, 0.f};
#pragma unroll
    for (int ee = 0; ee < 2; ee++) {
#pragma unroll
        for (int qi = 0; qi < 4; qi++) {
            uint32_t w4[4] = {q[ee * 4 + qi].x, q[ee * 4 + qi].y,
                              q[ee * 4 + qi].z, q[ee * 4 + qi].w};
#pragma unroll
            for (int u = 0; u < 4; u++) {
                float2 wf = __half22float2(*(__half2*)&w4[u]);
                int h = qi * 8 + 2 * u;
                float2 p0 = *(const float2*)&ns[w][ee * 2][h];
                float2 p1 = *(const float2*)&ns[w][ee * 2 + 1][h];
                acc[ee * 2] += p0.x * wf.x + p0.y * wf.y;
                acc[ee * 2 + 1] += p1.x * wf.x + p1.y * wf.y;
            }
        }
    }
#pragma unroll
    for (int ee = 0; ee < 2; ee++) {
        int d = ee ? d1 : d0;
        float a0 = acc[ee * 2], a1 = acc[ee * 2 + 1];
        float u = __shfl_down_sync(0xffffffffu, a0, 1);
        float v = __shfl_up_sync(0xffffffffu, a1, 1);
        if (!(lane & 1))
            asm volatile("red.global.add.v2.f32 [%0], {%1,%2};"
                         :: "l"(&g_agg[(size_t)d * 32 + lane]), "f"(a0), "f"(u)
                         : "memory");
        else
            asm volatile("red.global.add.v2.f32 [%0], {%1,%2};"
                         :: "l"(&g_agg[N32 + (size_t)d * 32 + lane - 1]), "f"(v),
                            "f"(a1)
                         : "memory");
    }
}

// ---- launch 3 (PROFILED): fused single-GEMM GRU, 96 nodes/block, 2 CTA/SM ---
// A[96x128] = [v_hi|v_lo|h_hi|h_lo]; B[128x128] cols = [r_sum|z_sum|x_n|h_n]
#define GA 0          // 96*136*2  = 26112
#define GB 26112      // 128*136*2 = 34816
#define GC 60928      // 96*132*4  = 50688
#define GBI 111616    // 192*4     = 768
#define GTOT 112384

__global__ __launch_bounds__(256, 2) void gru_kernel(const float* __restrict__ convb,
                                                     const float* __restrict__ wih,
                                                     const float* __restrict__ whh,
                                                     const float* __restrict__ bih,
                                                     const float* __restrict__ bhh,
                                                     float* __restrict__ outp) {
    extern __shared__ char sm[];
    __half* sA = (__half*)(sm + GA);
    __half* sB = (__half*)(sm + GB);
    float* sC = (float*)(sm + GC);
    float* sBI = (float*)(sm + GBI);
    int tid = threadIdx.x, wid = tid >> 5;
    size_t base = (size_t)blockIdx.x * 3072;

    // stage A: relu(agg+cb) hi/lo and hidden hi/lo; reset agg
#pragma unroll
    for (int i = 0; i < 12; i++) {
        int v = tid + i * 256, row = v >> 5, col = v & 31;
        float nf = fmaxf(g_agg[base + v] + convb[col], 0.f);
        g_agg[base + v] = 0.f;
        __half nh = __float2half(nf);
        sA[row * 136 + col] = nh;
        sA[row * 136 + 32 + col] = __float2half(nf - __half2float(nh));
        float hf = g_h[base + v];
        __half hh = __float2half(hf);
        sA[row * 136 + 64 + col] = hh;
        sA[row * 136 + 96 + col] = __float2half(hf - __half2float(hh));
    }
    // stage B: k<64 -> wih rows (sect 3 zero); k>=64 -> whh rows (sect 2 zero)
#pragma unroll
    for (int i = 0; i < 64; i++) {
        int v = tid + i * 256;
        int k = v >> 7, j = v & 127;
        int h = k & 31, sect = j >> 5, jj = j & 31;
        float val;
        if (k < 64)
            val = (sect == 3) ? 0.f : wih[(sect * 32 + jj) * 32 + h];
        else
            val = (sect == 2) ? 0.f
                              : whh[((sect == 3 ? 2 : sect) * 32 + jj) * 32 + h];
        sB[k * 136 + j] = __float2half(val);
    }
    if (tid < 96) { sBI[tid] = bih[tid]; sBI[96 + tid] = bhh[tid]; }
    __syncthreads();

    // GEMM [96x128]@[128x128]; warp wid owns output cols [wid*16, wid*16+16)
    wmma::fragment<wmma::matrix_b, 16, 16, 16, __half, wmma::row_major> bf[8];
#pragma unroll
    for (int k = 0; k < 8; k++)
        wmma::load_matrix_sync(bf[k], sB + (k * 16) * 136 + wid * 16, 136);
#pragma unroll 1
    for (int m = 0; m < 6; m++) {
        wmma::fragment<wmma::accumulator, 16, 16, 16, float> acc;
        wmma::fill_fragment(acc, 0.f);
#pragma unroll
        for (int k = 0; k < 8; k++) {
            wmma::fragment<wmma::matrix_a, 16, 16, 16, __half, wmma::row_major> af;
            wmma::load_matrix_sync(af, sA + (m * 16) * 136 + k * 16, 136);
            wmma::mma_sync(acc, af, bf[k], acc);
        }
        wmma::store_matrix_sync(sC + (m * 16) * 132 + wid * 16, acc, 132,
                                wmma::mem_row_major);
    }
    __syncthreads();

    // epilogue: gates + state update (hid recovered exactly from hi+lo)
#pragma unroll
    for (int i = 0; i < 12; i++) {
        int v = tid + i * 256, row = v >> 5, j = v & 31;
        const float* c = sC + row * 132;
        float r = fsig(c[j] + sBI[j] + sBI[96 + j]);
        float z = fsig(c[32 + j] + sBI[32 + j] + sBI[128 + j]);
        float n = ftanh(c[64 + j] + sBI[64 + j] + r * (c[96 + j] + sBI[160 + j]));
        float hid = __half2float(sA[row * 136 + 64 + j]) +
                    __half2float(sA[row * 136 + 96 + j]);
        float hn = (1.f - z) * n + z * hid;
        if (outp) outp[base + v] = hn;
        else g_h[base + v] = hn;
    }
}

// ------------------------- launch -------------------------------------------
extern "C" void kernel_launch(void* const* d_in, const int* in_sizes, int n_in,
                              void* d_out, int out_size) {
    const float* x     = (const float*)d_in[0];
    const float* rel   = (const float*)d_in[1];
    const float* pw1   = (const float*)d_in[2];
    const float* pb1   = (const float*)d_in[3];
    const float* pw2   = (const float*)d_in[4];
    const float* pb2   = (const float*)d_in[5];
    const float* ew1   = (const float*)d_in[6];
    const float* eb1   = (const float*)d_in[7];
    const float* ew2   = (const float*)d_in[8];
    const float* eb2   = (const float*)d_in[9];
    const float* convb = (const float*)d_in[10];
    const float* wih   = (const float*)d_in[11];
    const float* whh   = (const float*)d_in[12];
    const float* bih   = (const float*)d_in[13];
    const float* bhh   = (const float*)d_in[14];
    const int*   src   = (const int*)d_in[15];
    const int*   dst   = (const int*)d_in[16];
    float* out = (float*)d_out;

    cudaFuncSetAttribute(we_wmma_kernel,
                         cudaFuncAttributeMaxDynamicSharedMemorySize, STOT);
    cudaFuncSetAttribute(gru_kernel,
                         cudaFuncAttributeMaxDynamicSharedMemorySize, GTOT);
    pre_kernel<<<129 + 27648 + 1728, 256>>>(ew2, eb2, (const float4*)rel, ew1,
                                            eb1, x, pw1, pb1, pw2, pb2);
    we_wmma_kernel<<<NEDGES / 128, 256, STOT>>>();
    for (int step = 0; step < 3; step++) {
        msg_kernel<<<NEDGES / 16, 256>>>(src, dst);
        gru_kernel<<<1152, 256, GTOT>>>(convb, wih, whh, bih, bhh,
                                        step == 2 ? out : nullptr);
    }
}

// round 13
// speedup vs baseline: 1.1776x; 1.1776x over previous
#include <cuda_runtime.h>
#include <cuda_fp16.h>
#include <mma.h>
#include <cstdint>
#include <cstddef>
using namespace nvcuda;

#define NNODES 55296
#define NEDGES 221184
#define N32 (NNODES * 32)
#define NW 13824  // warps in pre/h0 node pass (1728 blocks x 8)

// ------------------------- device scratch -----------------------------------
__device__ __align__(256) float g_h[2 * N32];
__device__ __align__(256) float g_agg[2 * N32];
__device__ __align__(256) __half g_tA[(size_t)NEDGES * 32];   // t hi fp16
__device__ __align__(256) __half g_Bt[32 * 1024];             // B' permuted (We)
__device__ __align__(256) float g_biasp[1024];                // eb2 permuted
__device__ __align__(256) __half g_GB[128 * 128];             // fused GRU B matrix
__device__ __align__(256) __half g_We[(size_t)NEDGES * 1024]; // [e][j] j=(q,o,hl)

__device__ __forceinline__ float frcp(float x) {
    float r;
    asm("rcp.approx.f32 %0, %1;" : "=f"(r) : "f"(x));
    return r;
}
__device__ __forceinline__ float fsig(float x) { return frcp(1.f + __expf(-x)); }
__device__ __forceinline__ float ftanh(float x) {
    return 1.f - 2.f * frcp(1.f + __expf(2.f * x));
}
__device__ __forceinline__ uint64_t mkpol_ef() {
    uint64_t p;
    asm("createpolicy.fractional.L2::evict_first.b64 %0;" : "=l"(p));
    return p;
}
__device__ __forceinline__ uint4 ld_ef(const void* gp, uint64_t pol) {
    uint4 v;
    asm volatile("ld.global.nc.L2::cache_hint.v4.u32 {%0,%1,%2,%3}, [%4], %5;"
                 : "=r"(v.x), "=r"(v.y), "=r"(v.z), "=r"(v.w)
                 : "l"(gp), "l"(pol));
    return v;
}
__device__ __forceinline__ void st_ef(void* gp, uint4 v, uint64_t pol) {
    asm volatile("st.global.L2::cache_hint.v4.b32 [%0], {%1,%2,%3,%4}, %5;"
                 :: "l"(gp), "r"(v.x), "r"(v.y), "r"(v.z), "r"(v.w), "l"(pol)
                 : "memory");
}

// ---- launch 0: fused pre: We-B' + bias + t + GRU-B' + h0 + zero -------------
__global__ __launch_bounds__(256) void pre_kernel(
    const float* __restrict__ ew2, const float* __restrict__ eb2,
    const float4* __restrict__ rel4, const float* __restrict__ ew1,
    const float* __restrict__ eb1, const float* __restrict__ x,
    const float* __restrict__ pw1, const float* __restrict__ pb1,
    const float* __restrict__ pw2, const float* __restrict__ pb2,
    const float* __restrict__ wih, const float* __restrict__ whh) {
    int b = blockIdx.x, tid = threadIdx.x;
    if (b < 128) {               // We B' [32][1024]: col j = q*256+o*8+hl
        int i = b * 256 + tid;
        int k = i >> 10, j = i & 1023;
        int h = ((j >> 8) << 3) + (j & 7), o = (j >> 3) & 31;
        g_Bt[i] = __float2half(ew2[k * 1024 + h * 32 + o]);
    } else if (b == 128) {       // permuted bias
#pragma unroll
        for (int u = 0; u < 4; u++) {
            int j = tid * 4 + u;
            int h = ((j >> 8) << 3) + (j & 7), o = (j >> 3) & 31;
            g_biasp[j] = eb2[h * 32 + o];
        }
    } else if (b < 129 + 27648) {  // t = relu(rel@ew1+eb1) -> fp16
        int g = (b - 129) * 256 + tid;
        int e = g >> 5, k = g & 31;
        float4 r = rel4[e];
        float v = eb1[k] + r.x * ew1[k] + r.y * ew1[32 + k] +
                  r.z * ew1[64 + k] + r.w * ew1[96 + k];
        g_tA[(size_t)e * 32 + k] = __float2half(fmaxf(v, 0.f));
    } else if (b < 27777 + 64) {  // fused GRU B matrix [128][128]
        int i = (b - 27777) * 256 + tid;
        int k = i >> 7, j = i & 127;
        int h = k & 31, sect = j >> 5, jj = j & 31;
        float val;
        if (k < 64)
            val = (sect == 3) ? 0.f : wih[(sect * 32 + jj) * 32 + h];
        else
            val = (sect == 2) ? 0.f
                              : whh[((sect == 3 ? 2 : sect) * 32 + jj) * 32 + h];
        g_GB[i] = __float2half(val);
    } else {                     // h0 projection + zero g_agg (8 nodes/warp)
        int hb = b - 27841;      // 0..1727
        __shared__ float sW1[1024], sW2[1024];
        int lane = tid & 31;
#pragma unroll
        for (int i = 0; i < 8; i++)
            g_agg[hb * 256 + tid + i * 442368] = 0.f;
        for (int i = tid; i < 1024; i += 256) { sW1[i] = pw1[i]; sW2[i] = pw2[i]; }
        __syncthreads();
        int wbase = hb * 8 + (tid >> 5);
#pragma unroll 1
        for (int it = 0; it < 8; it++) {
            int gw = wbase + it * NW;
            float xr = x[(size_t)gw * 32 + lane];
            float t1 = pb1[lane];
#pragma unroll
            for (int h = 0; h < 32; h++)
                t1 = fmaf(__shfl_sync(0xffffffffu, xr, h), sW1[h * 32 + lane], t1);
            t1 = fmaxf(t1, 0.f);
            float o = pb2[lane];
#pragma unroll
            for (int h = 0; h < 32; h++)
                o = fmaf(__shfl_sync(0xffffffffu, t1, h), sW2[h * 32 + lane], o);
            g_h[(size_t)gw * 32 + lane] = o;
        }
    }
}

// ---- launch 1: We GEMM [128x32]@[32x1024] wmma (measured 187us, unchanged) --
#define SA 0                 // 128*40*2  = 10240
#define SB 10240             // 32*1032*2 = 66048
#define SC 76288             // 8*16*68*4 = 34816
#define SBIAS 111104         // 4096
#define STOT 115200

__global__ __launch_bounds__(256, 2) void we_wmma_kernel() {
    extern __shared__ char sm[];
    __half* sA = (__half*)(sm + SA);
    __half* sB = (__half*)(sm + SB);
    float* sC = (float*)(sm + SC);
    float* sBias = (float*)(sm + SBIAS);
    int tid = threadIdx.x, wid = tid >> 5, lane = tid & 31;
    uint64_t pol = mkpol_ef();

    const uint4* ga = (const uint4*)(g_tA + (size_t)blockIdx.x * 128 * 32);
#pragma unroll
    for (int r = 0; r < 2; r++) {
        int i = tid + r * 256, row = i >> 2, c = i & 3;
        *(uint4*)(sA + row * 40 + c * 8) = ga[i];
    }
    const uint4* gb = (const uint4*)(const void*)g_Bt;
#pragma unroll
    for (int r = 0; r < 16; r++) {
        int i = tid + r * 256, row = i >> 7, c = i & 127;
        *(uint4*)(sB + row * 1032 + c * 8) = gb[i];
    }
#pragma unroll
    for (int r = 0; r < 4; r++) sBias[tid + r * 256] = g_biasp[tid + r * 256];
    __syncthreads();

    float* sCw = sC + wid * 16 * 68;
    const int rsub = lane >> 3, ch = lane & 7;
    for (int nt = 0; nt < 16; nt++) {
        wmma::fragment<wmma::accumulator, 16, 16, 16, float> acc[4];
#pragma unroll
        for (int f = 0; f < 4; f++) wmma::fill_fragment(acc[f], 0.f);
#pragma unroll
        for (int k = 0; k < 2; k++) {
            wmma::fragment<wmma::matrix_a, 16, 16, 16, __half, wmma::row_major> af;
            wmma::load_matrix_sync(af, sA + (wid * 16) * 40 + k * 16, 40);
#pragma unroll
            for (int f = 0; f < 4; f++) {
                wmma::fragment<wmma::matrix_b, 16, 16, 16, __half, wmma::row_major> bf;
                wmma::load_matrix_sync(bf, sB + (k * 16) * 1032 + nt * 64 + f * 16,
                                       1032);
                wmma::mma_sync(acc[f], af, bf, acc[f]);
            }
        }
        __syncwarp();
#pragma unroll
        for (int f = 0; f < 4; f++)
            wmma::store_matrix_sync(sCw + f * 16, acc[f], 68, wmma::mem_row_major);
        __syncwarp();
        const float* bp = sBias + nt * 64 + ch * 8;
#pragma unroll
        for (int p = 0; p < 4; p++) {
            int row = p * 4 + rsub;
            const float* rp = sCw + row * 68 + ch * 8;
            float4 v0 = *(const float4*)rp;
            float4 v1 = *(const float4*)(rp + 4);
            __half2 a = __floats2half2_rn(v0.x + bp[0], v0.y + bp[1]);
            __half2 b2 = __floats2half2_rn(v0.z + bp[2], v0.w + bp[3]);
            __half2 c2 = __floats2half2_rn(v1.x + bp[4], v1.y + bp[5]);
            __half2 d2 = __floats2half2_rn(v1.z + bp[6], v1.w + bp[7]);
            int e = blockIdx.x * 128 + wid * 16 + row;
            uint4 pk = make_uint4(*(uint32_t*)&a, *(uint32_t*)&b2,
                                  *(uint32_t*)&c2, *(uint32_t*)&d2);
            st_ef((char*)(void*)g_We + (size_t)e * 2048 + nt * 128 + ch * 16, pk,
                  pol);
        }
        __syncwarp();
    }
}

// ---- msg + scatter, 2 edges per warp (DRAM-bound, ~roofline, unchanged) -----
__global__ __launch_bounds__(256) void msg_kernel(const int* __restrict__ src,
                                                  const int* __restrict__ dst) {
    __shared__ __align__(16) float ns[8][4][32];
    const int w = threadIdx.x >> 5, lane = threadIdx.x & 31;
    const int e0 = blockIdx.x * 16 + w * 2;
    uint64_t pol = mkpol_ef();
    int s0 = __ldg(&src[e0]), s1 = __ldg(&src[e0 + 1]);
    int d0 = __ldg(&dst[e0]), d1 = __ldg(&dst[e0 + 1]);
    ns[w][0][lane] = g_h[(size_t)s0 * 32 + lane];
    ns[w][1][lane] = g_h[N32 + (size_t)s0 * 32 + lane];
    ns[w][2][lane] = g_h[(size_t)s1 * 32 + lane];
    ns[w][3][lane] = g_h[N32 + (size_t)s1 * 32 + lane];
    uint4 q[8];
#pragma unroll
    for (int ee = 0; ee < 2; ee++)
#pragma unroll
        for (int qi = 0; qi < 4; qi++)
            q[ee * 4 + qi] = ld_ef((const char*)(const void*)g_We +
                                       (size_t)(e0 + ee) * 2048 + qi * 512 +
                                       lane * 16,
                                   pol);
    __syncwarp();
    float acc[4] = {0.f, 0.f, 0.f, 0.f};
#pragma unroll
    for (int ee = 0; ee < 2; ee++) {
#pragma unroll
        for (int qi = 0; qi < 4; qi++) {
            uint32_t w4[4] = {q[ee * 4 + qi].x, q[ee * 4 + qi].y,
                              q[ee * 4 + qi].z, q[ee * 4 + qi].w};
#pragma unroll
            for (int u = 0; u < 4; u++) {
                float2 wf = __half22float2(*(__half2*)&w4[u]);
                int h = qi * 8 + 2 * u;
                float2 p0 = *(const float2*)&ns[w][ee * 2][h];
                float2 p1 = *(const float2*)&ns[w][ee * 2 + 1][h];
                acc[ee * 2] += p0.x * wf.x + p0.y * wf.y;
                acc[ee * 2 + 1] += p1.x * wf.x + p1.y * wf.y;
            }
        }
    }
#pragma unroll
    for (int ee = 0; ee < 2; ee++) {
        int d = ee ? d1 : d0;
        float a0 = acc[ee * 2], a1 = acc[ee * 2 + 1];
        float u = __shfl_down_sync(0xffffffffu, a0, 1);
        float v = __shfl_up_sync(0xffffffffu, a1, 1);
        if (!(lane & 1))
            asm volatile("red.global.add.v2.f32 [%0], {%1,%2};"
                         :: "l"(&g_agg[(size_t)d * 32 + lane]), "f"(a0), "f"(u)
                         : "memory");
        else
            asm volatile("red.global.add.v2.f32 [%0], {%1,%2};"
                         :: "l"(&g_agg[N32 + (size_t)d * 32 + lane - 1]), "f"(v),
                            "f"(a1)
                         : "memory");
    }
}

// ---- launch 3 (PROFILED): fused single-GEMM GRU, prebuilt B, 2 CTA/SM -------
// A[96x128] = [v_hi|v_lo|h_hi|h_lo]; B from g_GB; cols = [r_sum|z_sum|x_n|h_n]
#define GA 0          // 96*136*2  = 26112
#define GB 26112      // 128*136*2 = 34816
#define GC 60928      // 96*132*4  = 50688
#define GBI 111616    // 192*4     = 768
#define GTOT 112384

__global__ __launch_bounds__(256, 2) void gru_kernel(const float* __restrict__ convb,
                                                     const float* __restrict__ bih,
                                                     const float* __restrict__ bhh,
                                                     float* __restrict__ outp) {
    extern __shared__ char sm[];
    __half* sA = (__half*)(sm + GA);
    __half* sB = (__half*)(sm + GB);
    float* sC = (float*)(sm + GC);
    float* sBI = (float*)(sm + GBI);
    int tid = threadIdx.x, wid = tid >> 5;
    size_t base = (size_t)blockIdx.x * 3072;

    // stage A: relu(agg+cb) hi/lo and hidden hi/lo; reset agg
#pragma unroll
    for (int i = 0; i < 12; i++) {
        int v = tid + i * 256, row = v >> 5, col = v & 31;
        float nf = fmaxf(g_agg[base + v] + convb[col], 0.f);
        g_agg[base + v] = 0.f;
        __half nh = __float2half(nf);
        sA[row * 136 + col] = nh;
        sA[row * 136 + 32 + col] = __float2half(nf - __half2float(nh));
        float hf = g_h[base + v];
        __half hh = __float2half(hf);
        sA[row * 136 + 64 + col] = hh;
        sA[row * 136 + 96 + col] = __float2half(hf - __half2float(hh));
    }
    // stage B: vectorized copy of prebuilt fused matrix (8 uint4 iters)
    {
        const uint4* gB4 = (const uint4*)(const void*)g_GB;
#pragma unroll
        for (int r = 0; r < 8; r++) {
            int v = tid + r * 256, row = v >> 4, c = v & 15;
            *(uint4*)(sB + row * 136 + c * 8) = gB4[v];
        }
    }
    if (tid < 96) { sBI[tid] = bih[tid]; sBI[96 + tid] = bhh[tid]; }
    __syncthreads();

    // GEMM [96x128]@[128x128]; warp wid owns output cols [wid*16, wid*16+16)
    wmma::fragment<wmma::matrix_b, 16, 16, 16, __half, wmma::row_major> bf[8];
#pragma unroll
    for (int k = 0; k < 8; k++)
        wmma::load_matrix_sync(bf[k], sB + (k * 16) * 136 + wid * 16, 136);
#pragma unroll 1
    for (int m = 0; m < 6; m++) {
        wmma::fragment<wmma::accumulator, 16, 16, 16, float> acc;
        wmma::fill_fragment(acc, 0.f);
#pragma unroll
        for (int k = 0; k < 8; k++) {
            wmma::fragment<wmma::matrix_a, 16, 16, 16, __half, wmma::row_major> af;
            wmma::load_matrix_sync(af, sA + (m * 16) * 136 + k * 16, 136);
            wmma::mma_sync(acc, af, bf[k], acc);
        }
        wmma::store_matrix_sync(sC + (m * 16) * 132 + wid * 16, acc, 132,
                                wmma::mem_row_major);
    }
    __syncthreads();

    // epilogue: gates + state update (hid recovered exactly from hi+lo)
#pragma unroll
    for (int i = 0; i < 12; i++) {
        int v = tid + i * 256, row = v >> 5, j = v & 31;
        const float* c = sC + row * 132;
        float r = fsig(c[j] + sBI[j] + sBI[96 + j]);
        float z = fsig(c[32 + j] + sBI[32 + j] + sBI[128 + j]);
        float n = ftanh(c[64 + j] + sBI[64 + j] + r * (c[96 + j] + sBI[160 + j]));
        float hid = __half2float(sA[row * 136 + 64 + j]) +
                    __half2float(sA[row * 136 + 96 + j]);
        float hn = (1.f - z) * n + z * hid;
        if (outp) outp[base + v] = hn;
        else g_h[base + v] = hn;
    }
}

// ------------------------- launch -------------------------------------------
extern "C" void kernel_launch(void* const* d_in, const int* in_sizes, int n_in,
                              void* d_out, int out_size) {
    const float* x     = (const float*)d_in[0];
    const float* rel   = (const float*)d_in[1];
    const float* pw1   = (const float*)d_in[2];
    const float* pb1   = (const float*)d_in[3];
    const float* pw2   = (const float*)d_in[4];
    const float* pb2   = (const float*)d_in[5];
    const float* ew1   = (const float*)d_in[6];
    const float* eb1   = (const float*)d_in[7];
    const float* ew2   = (const float*)d_in[8];
    const float* eb2   = (const float*)d_in[9];
    const float* convb = (const float*)d_in[10];
    const float* wih   = (const float*)d_in[11];
    const float* whh   = (const float*)d_in[12];
    const float* bih   = (const float*)d_in[13];
    const float* bhh   = (const float*)d_in[14];
    const int*   src   = (const int*)d_in[15];
    const int*   dst   = (const int*)d_in[16];
    float* out = (float*)d_out;

    cudaFuncSetAttribute(we_wmma_kernel,
                         cudaFuncAttributeMaxDynamicSharedMemorySize, STOT);
    cudaFuncSetAttribute(gru_kernel,
                         cudaFuncAttributeMaxDynamicSharedMemorySize, GTOT);
    pre_kernel<<<27841 + 1728, 256>>>(ew2, eb2, (const float4*)rel, ew1, eb1,
                                      x, pw1, pb1, pw2, pb2, wih, whh);
    we_wmma_kernel<<<NEDGES / 128, 256, STOT>>>();
    for (int step = 0; step < 3; step++) {
        msg_kernel<<<NEDGES / 16, 256>>>(src, dst);
        gru_kernel<<<1152, 256, GTOT>>>(convb, bih, bhh,
                                        step == 2 ? out : nullptr);
    }
}